// round 1
// baseline (speedup 1.0000x reference)
#include <cuda_runtime.h>

#define R_RUNS 128
#define T_STEPS 1024
#define N_AGENTS 128
#define NT 64      // threads per block = N_AGENTS/2
#define PF 4       // prefetch depth (phases ahead)
#define NPHASE 1087

__device__ __forceinline__ float ex2_approx(float x) {
    float r;
    asm("ex2.approx.f32 %0, %1;" : "=f"(r) : "f"(x));
    return r;
}
__device__ __forceinline__ float rcp_approx(float x) {
    float r;
    asm("rcp.approx.f32 %0, %1;" : "=f"(r) : "f"(x));
    return r;
}

__global__ __launch_bounds__(NT, 1)
void com2net_wavefront(const float* __restrict__ runs,
                       const float* __restrict__ W1,
                       const float* __restrict__ b1,
                       const float* __restrict__ W2,
                       const float* __restrict__ b2,
                       float* __restrict__ out)
{
    const int tid = threadIdx.x;
    const int r   = blockIdx.x;

    // Parity-compacted comm buffers (conflict-free, stride-1 access):
    //   cA[k] = a-input (comm[2i]) for even agent i=2k
    //   cB[k] = b-input (comm[2i+3]) for odd agent i=2k+1
    __shared__ float cA[NT + 2];
    __shared__ float cB[NT + 2];
    cA[tid] = 0.0f;
    cB[tid] = 0.0f;
    if (tid < 2) { cA[NT + tid] = 0.0f; cB[NT + tid] = 0.0f; }

    // ---- load + prescale weights into registers ----
    // tanh(x) = 2*sigma(2x)-1 ; sigma(2x) = 1/(1+2^(-2*log2e*x))
    // layer1 emits y = S*(W1@inp + b1), S = -2*log2(e); then e=2^y, s=1/(1+e)
    // layer2: out = (2*W2)@s + (b2 - W2@1)
    const float S = -2.8853900817779268f;  // -2/ln(2)
    float u0[10], u1[10], u2[10], u3[10], c1[10];
#pragma unroll
    for (int j = 0; j < 10; ++j) {
        u0[j] = W1[j * 4 + 0] * S;
        u1[j] = W1[j * 4 + 1] * S;
        u2[j] = W1[j * 4 + 2] * S;
        u3[j] = W1[j * 4 + 3] * S;
        c1[j] = b1[j] * S;
    }
    float v0[10], v1[10], v2[10], c20, c21, c22;
    {
        float s0 = 0.f, s1 = 0.f, s2 = 0.f;
#pragma unroll
        for (int j = 0; j < 10; ++j) {
            float w0 = W2[0 * 10 + j], w1 = W2[1 * 10 + j], w2 = W2[2 * 10 + j];
            v0[j] = 2.f * w0; v1[j] = 2.f * w1; v2[j] = 2.f * w2;
            s0 += w0; s1 += w1; s2 += w2;
        }
        c20 = b2[0] - s0; c21 = b2[1] - s1; c22 = b2[2] - s2;
    }

    // lane handles agents iA=2*tid (even levels) and iB=2*tid+1 (odd levels);
    // within a phase p, both are at timestep t = p - tid.
    const float* xbase = runs + (size_t)r * T_STEPS * N_AGENTS * 2 + (size_t)tid * 4;
    float*       obase = out  + (size_t)r * T_STEPS * N_AGENTS     + (size_t)tid * 2;

    // ---- prefetch queue: xq[d] holds xs(t = p - tid + d) ----
    float4 xq[PF];
#pragma unroll
    for (int d = 0; d < PF; ++d) {
        int tc = d - tid;
        tc = max(0, min(T_STEPS - 1, tc));
        xq[d] = *(const float4*)(xbase + (size_t)tc * (N_AGENTS * 2));
    }

    float bA = 0.0f;  // b-input for MLP-A: o1 of own MLP-B from previous phase

    __syncthreads();

#pragma unroll 1
    for (int p = 0; p < NPHASE; ++p) {
        // issue prefetch for t + PF early
        int tl = p - tid + PF;
        tl = max(0, min(T_STEPS - 1, tl));
        const float4 xnew = *(const float4*)(xbase + (size_t)tl * (N_AGENTS * 2));

        const int t = p - tid;
        const bool act = ((unsigned)t < (unsigned)T_STEPS);
        const float4 x = xq[0];
        xq[0] = xq[1]; xq[1] = xq[2]; xq[2] = xq[3]; xq[3] = xnew;

        float o0A = 0.f, o1A = 0.f, aB = 0.f;
        if (act) {
            const float a = cA[tid];   // from lane tid-1's MLP-B (prev phase)
            const float b = bA;        // own register
            float s[10];
#pragma unroll
            for (int j = 0; j < 10; ++j) {
                float y = fmaf(u3[j], b, c1[j]);
                y = fmaf(u2[j], a, y);
                y = fmaf(u1[j], x.y, y);
                y = fmaf(u0[j], x.x, y);
                s[j] = rcp_approx(ex2_approx(y) + 1.0f);
            }
            float p0a = c20, p0b = 0.f, p1a = c21, p1b = 0.f, p2a = c22, p2b = 0.f;
#pragma unroll
            for (int j = 0; j < 10; j += 2) {
                p0a = fmaf(v0[j], s[j], p0a); p0b = fmaf(v0[j + 1], s[j + 1], p0b);
                p1a = fmaf(v1[j], s[j], p1a); p1b = fmaf(v1[j + 1], s[j + 1], p1b);
                p2a = fmaf(v2[j], s[j], p2a); p2b = fmaf(v2[j + 1], s[j + 1], p2b);
            }
            o0A = p0a + p0b; o1A = p1a + p1b; aB = p2a + p2b;
            if (tid > 0) cB[tid - 1] = o1A;  // -> b-input of agent 2tid-1 (lane tid-1 MLP-B, this phase)
        }
        __syncthreads();

        if (act) {
            const float b = cB[tid];   // from lane tid+1's MLP-A (this phase)
            const float a = aB;        // o2 of own MLP-A (this phase)
            float s[10];
#pragma unroll
            for (int j = 0; j < 10; ++j) {
                float y = fmaf(u3[j], b, c1[j]);
                y = fmaf(u2[j], a, y);
                y = fmaf(u1[j], x.w, y);
                y = fmaf(u0[j], x.z, y);
                s[j] = rcp_approx(ex2_approx(y) + 1.0f);
            }
            float p0a = c20, p0b = 0.f, p1a = c21, p1b = 0.f, p2a = c22, p2b = 0.f;
#pragma unroll
            for (int j = 0; j < 10; j += 2) {
                p0a = fmaf(v0[j], s[j], p0a); p0b = fmaf(v0[j + 1], s[j + 1], p0b);
                p1a = fmaf(v1[j], s[j], p1a); p1b = fmaf(v1[j + 1], s[j + 1], p1b);
                p2a = fmaf(v2[j], s[j], p2a); p2b = fmaf(v2[j + 1], s[j + 1], p2b);
            }
            const float o0B = p0a + p0b;
            bA = p1a + p1b;                       // -> own MLP-A b-input next phase
            cA[tid + 1] = p2a + p2b;              // -> lane tid+1 MLP-A a-input next phase
            // store controls[r][t][2tid], [2tid+1] as one 8B store
            *(float2*)(obase + (size_t)t * N_AGENTS) = make_float2(o0A, o0B);
        }
        __syncthreads();
    }
}

extern "C" void kernel_launch(void* const* d_in, const int* in_sizes, int n_in,
                              void* d_out, int out_size)
{
    const float* runs = (const float*)d_in[0];
    const float* W1   = (const float*)d_in[1];
    const float* b1   = (const float*)d_in[2];
    const float* W2   = (const float*)d_in[3];
    const float* b2   = (const float*)d_in[4];
    float* out = (float*)d_out;
    com2net_wavefront<<<R_RUNS, NT>>>(runs, W1, b1, W2, b2, out);
}